// round 2
// baseline (speedup 1.0000x reference)
#include <cuda_runtime.h>
#include <math.h>

#define Bz   128
#define Tz   1024
#define INz  256
#define Hz   512
#define G4   2048   // 4*H
#define NCTA 128    // persistent grid for the recurrent kernel

// ---------------- scratch (device globals: no cudaMalloc allowed) ----------
__device__ float g_xg[(size_t)Bz * Tz * G4];   // gate preactivations, 1.07 GB (reused by both layers)
__device__ float g_hs[(size_t)Bz * Tz * Hz];   // layer-0 hidden outputs, 268 MB
__device__ float g_hbuf[2][Bz * Hz];           // double-buffered h exchange
__device__ unsigned g_gen;                     // barrier generation
__device__ int g_cnt;                          // barrier arrival count

// ---------------------------------------------------------------------------
// Zero the h exchange buffers (c lives in registers, init 0 there)
// ---------------------------------------------------------------------------
__global__ void zero_hbuf_kernel() {
    int i = blockIdx.x * blockDim.x + threadIdx.x;
    if (i < 2 * Bz * Hz) ((float*)g_hbuf)[i] = 0.0f;
}

// ---------------------------------------------------------------------------
// Y[m][n] = dot(X[m,:], W[n,:]) + b1[n] + b2[n]      (Y = g_xg, N = 2048)
// M = B*T = 131072. BM=BN=64, BK=32, 256 threads, 4x4 per thread.
// Thread n-cols are spread (nl, nl+16, nl+32, nl+48) -> conflict-free LDS.128.
// ---------------------------------------------------------------------------
template <int K, bool XFROMHS>
__global__ void __launch_bounds__(256) gemm_bias_kernel(
    const float* __restrict__ Xin,
    const float* __restrict__ W,
    const float* __restrict__ b1,
    const float* __restrict__ b2)
{
    __shared__ float As[64][36];
    __shared__ float Bs[64][36];

    const float* __restrict__ X = XFROMHS ? (const float*)g_hs : Xin;

    int tid = threadIdx.x;
    int m0g = blockIdx.y * 64;
    int n0g = blockIdx.x * 64;
    int nl  = tid & 15;          // n lane: cols nl + 16*j
    int mg  = tid >> 4;          // 0..15
    int m0  = mg * 4;            // 4 rows per thread

    float acc[4][4];
#pragma unroll
    for (int i = 0; i < 4; i++)
#pragma unroll
        for (int j = 0; j < 4; j++) acc[i][j] = 0.0f;

    for (int kt = 0; kt < K; kt += 32) {
#pragma unroll
        for (int i = 0; i < 2; i++) {
            int li = tid * 2 + i;          // 0..511
            int r = li >> 3, kq = li & 7;
            *(float4*)&As[r][kq * 4] =
                *(const float4*)&X[(size_t)(m0g + r) * K + kt + kq * 4];
        }
#pragma unroll
        for (int i = 0; i < 2; i++) {
            int li = tid * 2 + i;
            int r = li >> 3, kq = li & 7;
            *(float4*)&Bs[r][kq * 4] =
                *(const float4*)&W[(size_t)(n0g + r) * K + kt + kq * 4];
        }
        __syncthreads();
#pragma unroll
        for (int k4 = 0; k4 < 8; k4++) {
            float4 a[4], bb[4];
#pragma unroll
            for (int i = 0; i < 4; i++) a[i] = *(float4*)&As[m0 + i][k4 * 4];
#pragma unroll
            for (int j = 0; j < 4; j++) bb[j] = *(float4*)&Bs[nl + 16 * j][k4 * 4];
#pragma unroll
            for (int i = 0; i < 4; i++) {
#pragma unroll
                for (int j = 0; j < 4; j++) {
                    acc[i][j] = fmaf(a[i].x, bb[j].x, acc[i][j]);
                    acc[i][j] = fmaf(a[i].y, bb[j].y, acc[i][j]);
                    acc[i][j] = fmaf(a[i].z, bb[j].z, acc[i][j]);
                    acc[i][j] = fmaf(a[i].w, bb[j].w, acc[i][j]);
                }
            }
        }
        __syncthreads();
    }

#pragma unroll
    for (int j = 0; j < 4; j++) {
        int n = n0g + nl + 16 * j;
        float bias = b1[n] + b2[n];
#pragma unroll
        for (int i = 0; i < 4; i++) {
            int m = m0g + m0 + i;
            g_xg[(size_t)m * G4 + n] = acc[i][j] + bias;
        }
    }
}

// ---------------------------------------------------------------------------
// Persistent recurrent kernel: 128 CTAs, grid barrier per time step.
// CTA = (batch tile of 32) x (16 hidden cols => 64 gate cols, 4 gates).
// Thread owns 2 batch rows x (the 4 gates of 1 hidden col): c stays in regs,
// elementwise update needs no inter-thread exchange.
// ---------------------------------------------------------------------------
__global__ void __launch_bounds__(256) lstm_seq_kernel(
    const float* __restrict__ w_hh,   // [4H][H]
    int store_hs)
{
    __shared__ float Hs[32][36];
    __shared__ float Ws[64][36];

    int tid = threadIdx.x;
    int bt = blockIdx.x & 3;          // 4 batch tiles of 32
    int ct = blockIdx.x >> 2;         // 32 col tiles of 16
    int b0 = bt * 32;
    int j0 = ct * 16;
    int jl = tid & 15;                // hidden col within tile
    int rp = tid >> 4;                // row pair 0..15
    int r0 = rp * 2;
    int jglob = j0 + jl;

    float c0 = 0.0f, c1 = 0.0f;
    int cur = 0;

#pragma unroll 1
    for (int t = 0; t < Tz; t++) {
        float acc[2][4];
#pragma unroll
        for (int r = 0; r < 2; r++)
#pragma unroll
            for (int g = 0; g < 4; g++) acc[r][g] = 0.0f;

        const float* __restrict__ hb = &g_hbuf[cur][0];

        for (int kt = 0; kt < Hz; kt += 32) {
            {   // Hs: 32x32, 1 float4/thread (L2 read, bypass L1: cross-CTA data)
                int r = tid >> 3, kq = tid & 7;
                *(float4*)&Hs[r][kq * 4] =
                    __ldcg((const float4*)&hb[(size_t)(b0 + r) * Hz + kt + kq * 4]);
            }
#pragma unroll
            for (int i = 0; i < 2; i++) {   // Ws: 64x32, 2 float4/thread
                int li = tid * 2 + i;
                int gc = li >> 3, kq = li & 7;
                int gate = gc >> 4, jj = gc & 15;
                *(float4*)&Ws[gc][kq * 4] =
                    *(const float4*)&w_hh[(size_t)(gate * Hz + j0 + jj) * Hz + kt + kq * 4];
            }
            __syncthreads();
#pragma unroll
            for (int k4 = 0; k4 < 8; k4++) {
                float4 h0 = *(float4*)&Hs[r0][k4 * 4];
                float4 h1 = *(float4*)&Hs[r0 + 1][k4 * 4];
#pragma unroll
                for (int g = 0; g < 4; g++) {
                    float4 w = *(float4*)&Ws[jl + 16 * g][k4 * 4];
                    acc[0][g] = fmaf(h0.x, w.x, acc[0][g]);
                    acc[0][g] = fmaf(h0.y, w.y, acc[0][g]);
                    acc[0][g] = fmaf(h0.z, w.z, acc[0][g]);
                    acc[0][g] = fmaf(h0.w, w.w, acc[0][g]);
                    acc[1][g] = fmaf(h1.x, w.x, acc[1][g]);
                    acc[1][g] = fmaf(h1.y, w.y, acc[1][g]);
                    acc[1][g] = fmaf(h1.z, w.z, acc[1][g]);
                    acc[1][g] = fmaf(h1.w, w.w, acc[1][g]);
                }
            }
            __syncthreads();
        }

        // add xg, gate nonlinearities, cell/hidden update
        float* __restrict__ hnext = &g_hbuf[cur ^ 1][0];
#pragma unroll
        for (int rr = 0; rr < 2; rr++) {
            int b = b0 + r0 + rr;
            size_t base = ((size_t)b * Tz + t) * G4;
            float gi = acc[rr][0] + g_xg[base + 0 * Hz + jglob];
            float gf = acc[rr][1] + g_xg[base + 1 * Hz + jglob];
            float gg = acc[rr][2] + g_xg[base + 2 * Hz + jglob];
            float go = acc[rr][3] + g_xg[base + 3 * Hz + jglob];
            float i_ = 1.0f / (1.0f + __expf(-gi));
            float f_ = 1.0f / (1.0f + __expf(-gf));
            float g_ = tanhf(gg);
            float o_ = 1.0f / (1.0f + __expf(-go));
            float c  = rr ? c1 : c0;
            c = f_ * c + i_ * g_;
            if (rr) c1 = c; else c0 = c;
            float h = o_ * tanhf(c);
            hnext[(size_t)b * Hz + jglob] = h;
            if (store_hs) g_hs[((size_t)b * Tz + t) * Hz + jglob] = h;
        }
        cur ^= 1;

        // ------------- grid barrier (sense via generation counter) ----------
        __threadfence();           // release this thread's h stores (all threads)
        __syncthreads();
        if (tid == 0) {
            unsigned g = *(volatile unsigned*)&g_gen;   // read epoch BEFORE arriving
            int old = atomicAdd(&g_cnt, 1);
            if (old == NCTA - 1) {
                atomicExch(&g_cnt, 0);
                __threadfence();
                atomicAdd(&g_gen, 1);
            } else {
                while (*(volatile unsigned*)&g_gen == g) { }
            }
            __threadfence();       // acquire
        }
        __syncthreads();
    }
}

// ---------------------------------------------------------------------------
// Head: last = h1[:, T-1, :] (lives in g_hbuf[0] after 1024 steps);
// z = relu(last@fc_wT + fc_b); out = sigmoid(z@fc2_wT + fc2_b)
// ---------------------------------------------------------------------------
__global__ void head_kernel(const float* __restrict__ fc_w,
                            const float* __restrict__ fc_b,
                            const float* __restrict__ fc2_w,
                            const float* __restrict__ fc2_b,
                            float* __restrict__ out)
{
    int b = blockIdx.x;      // 128 blocks
    int f = threadIdx.x;     // 64 threads
    const float* hb = &g_hbuf[0][b * Hz];
    float s = 0.0f;
    for (int k = 0; k < Hz; k += 4) {
        float4 hv = *(const float4*)&hb[k];
        float4 wv = *(const float4*)&fc_w[(size_t)f * Hz + k];
        s = fmaf(hv.x, wv.x, s);
        s = fmaf(hv.y, wv.y, s);
        s = fmaf(hv.z, wv.z, s);
        s = fmaf(hv.w, wv.w, s);
    }
    s += fc_b[f];
    s = fmaxf(s, 0.0f);
    float v = s * fc2_w[f];

    __shared__ float red[64];
    red[f] = v;
    __syncthreads();
    if (f == 0) {
        float z = 0.0f;
#pragma unroll
        for (int i = 0; i < 64; i++) z += red[i];
        z += fc2_b[0];
        out[b] = 1.0f / (1.0f + expf(-z));
    }
}

// ---------------------------------------------------------------------------
extern "C" void kernel_launch(void* const* d_in, const int* in_sizes, int n_in,
                              void* d_out, int out_size)
{
    const float* x      = (const float*)d_in[0];
    // d_in[1] = length_list (int32) — unused by reference semantics
    const float* w_ih0  = (const float*)d_in[2];
    const float* w_hh0  = (const float*)d_in[3];
    const float* b_ih0  = (const float*)d_in[4];
    const float* b_hh0  = (const float*)d_in[5];
    const float* w_ih1  = (const float*)d_in[6];
    const float* w_hh1  = (const float*)d_in[7];
    const float* b_ih1  = (const float*)d_in[8];
    const float* b_hh1  = (const float*)d_in[9];
    const float* fc_w   = (const float*)d_in[10];
    const float* fc_b   = (const float*)d_in[11];
    const float* fc2_w  = (const float*)d_in[12];
    const float* fc2_b  = (const float*)d_in[13];
    float* out = (float*)d_out;

    dim3 ggrid(G4 / 64, (Bz * Tz) / 64);   // (32, 2048)

    // Layer 0
    zero_hbuf_kernel<<<(2 * Bz * Hz + 255) / 256, 256>>>();
    gemm_bias_kernel<INz, false><<<ggrid, 256>>>(x, w_ih0, b_ih0, b_hh0);
    lstm_seq_kernel<<<NCTA, 256>>>(w_hh0, 1);

    // Layer 1
    zero_hbuf_kernel<<<(2 * Bz * Hz + 255) / 256, 256>>>();
    gemm_bias_kernel<Hz, true><<<ggrid, 256>>>(nullptr, w_ih1, b_ih1, b_hh1);
    lstm_seq_kernel<<<NCTA, 256>>>(w_hh1, 0);

    // FC head
    head_kernel<<<Bz, 64>>>(fc_w, fc_b, fc2_w, fc2_b, out);
}

// round 3
// speedup vs baseline: 2.3340x; 2.3340x over previous
#include <cuda_runtime.h>
#include <math.h>
#include <stdint.h>

#define Bz   128
#define Tz   1024
#define INz  256
#define Hz   512
#define G4   2048   // 4*H
#define NCTA 128

// ---------------- scratch (device globals) ---------------------------------
__device__ float g_xg[(size_t)Bz * Tz * G4];    // gate preacts, PERMUTED cols (jj*4+gate)
__device__ float g_hs[(size_t)Bz * Tz * Hz];    // layer-0 hidden outputs (plain layout)
__device__ float g_ph[2][Bz * Hz];              // h exchange, A-frag-permuted per 32-row batch tile
__device__ float g_hlast[Bz * Hz];              // final h of the running layer
__device__ unsigned g_gen;
__device__ int g_cnt;

// ---------------------------------------------------------------------------
__device__ __forceinline__ float rna_tf32(float x) {
    unsigned u;
    asm("cvt.rna.tf32.f32 %0, %1;" : "=r"(u) : "f"(x));
    return __uint_as_float(u);
}
__device__ __forceinline__ void mma_tf32(float* d, const uint4& a, const uint2& b) {
    asm volatile(
        "mma.sync.aligned.m16n8k8.row.col.f32.tf32.tf32.f32 "
        "{%0,%1,%2,%3}, {%4,%5,%6,%7}, {%8,%9}, {%0,%1,%2,%3};\n"
        : "+f"(d[0]), "+f"(d[1]), "+f"(d[2]), "+f"(d[3])
        : "r"(a.x), "r"(a.y), "r"(a.z), "r"(a.w), "r"(b.x), "r"(b.y));
}
__device__ __forceinline__ float sigf(float x) { return 1.0f / (1.0f + __expf(-x)); }

// ---------------------------------------------------------------------------
__global__ void zero_ph_kernel() {
    int i = blockIdx.x * blockDim.x + threadIdx.x;
    if (i < 2 * Bz * Hz) ((float*)g_ph)[i] = 0.0f;
}

// ---------------------------------------------------------------------------
// Input GEMM: g_xg[m][n'] = sum_k X[m][k] * W[row(n')][k] + b1[row]+b2[row]
// n' = jj*4 + gate  (permuted),  row(n') = (n'&3)*Hz + (n'>>2)
// BM=128, BN=64, BK=16, 256 thr (8 warps = 4m x 2n, warp tile 32x32), tf32 mma.
// ---------------------------------------------------------------------------
template <int K, bool XFROMHS>
__global__ void __launch_bounds__(256) gemm_tf32_kernel(
    const float* __restrict__ Xin, const float* __restrict__ W,
    const float* __restrict__ b1, const float* __restrict__ b2)
{
    __shared__ float Asm[8][2][32][4];   // [m16 tile][kstep][lane][a0..a3]  8KB
    __shared__ float Bsm[8][2][32][2];   // [n8 tile][kstep][lane][b0,b1]    4KB
    __shared__ float sbias[64];

    const float* __restrict__ X = XFROMHS ? (const float*)g_hs : Xin;

    int tid  = threadIdx.x;
    int lane = tid & 31, warp = tid >> 5;
    int wm = warp & 3, wn = warp >> 2;
    int g  = lane >> 2, tig = lane & 3;
    size_t m0g = (size_t)blockIdx.y * 128;
    int    n0g = blockIdx.x * 64;

    if (tid < 64) {
        int ng  = n0g + tid;
        int row = (ng & 3) * Hz + (ng >> 2);
        sbias[tid] = b1[row] + b2[row];
    }

    float d[2][4][4];
#pragma unroll
    for (int a = 0; a < 2; a++)
#pragma unroll
        for (int b = 0; b < 4; b++)
#pragma unroll
            for (int c = 0; c < 4; c++) d[a][b][c] = 0.0f;

    // B fill mapping (fixed per thread)
    int fn = tid >> 2, fq = tid & 3;
    int brow = ((n0g + fn) & 3) * Hz + ((n0g + fn) >> 2);
    const float* bbase = &W[(size_t)brow * K + fq * 4];
    int bt_ = fn >> 3, bg = fn & 7;
    int bks = fq >> 1, bp = fq & 1;

    for (int kb = 0; kb < K; kb += 16) {
        // ---- A tile fill (frag-permuted, rounded to tf32) ----
#pragma unroll
        for (int i = 0; i < 2; i++) {
            int f4 = tid * 2 + i;
            int m = f4 >> 2, q = f4 & 3;
            float4 v = *(const float4*)&X[(m0g + m) * K + kb + q * 4];
            int mt = m >> 4, r = m & 15, gg = r & 7, ii = r >> 3;
            int ks = q >> 1, jj = q & 1, e = ii + 2 * jj;
            Asm[mt][ks][gg * 4 + 0][e] = rna_tf32(v.x);
            Asm[mt][ks][gg * 4 + 1][e] = rna_tf32(v.y);
            Asm[mt][ks][gg * 4 + 2][e] = rna_tf32(v.z);
            Asm[mt][ks][gg * 4 + 3][e] = rna_tf32(v.w);
        }
        // ---- B tile fill ----
        {
            float4 v = *(const float4*)&bbase[kb];
            Bsm[bt_][bks][bg * 4 + 0][bp] = rna_tf32(v.x);
            Bsm[bt_][bks][bg * 4 + 1][bp] = rna_tf32(v.y);
            Bsm[bt_][bks][bg * 4 + 2][bp] = rna_tf32(v.z);
            Bsm[bt_][bks][bg * 4 + 3][bp] = rna_tf32(v.w);
        }
        __syncthreads();
#pragma unroll
        for (int ks = 0; ks < 2; ks++) {
            uint4 a0 = *(uint4*)&Asm[wm * 2 + 0][ks][lane][0];
            uint4 a1 = *(uint4*)&Asm[wm * 2 + 1][ks][lane][0];
#pragma unroll
            for (int j = 0; j < 4; j++) {
                uint2 bb = *(uint2*)&Bsm[wn * 4 + j][ks][lane][0];
                mma_tf32(d[0][j], a0, bb);
                mma_tf32(d[1][j], a1, bb);
            }
        }
        __syncthreads();
    }

    // ---- epilogue: add bias, store permuted ----
#pragma unroll
    for (int mt = 0; mt < 2; mt++) {
#pragma unroll
        for (int j = 0; j < 4; j++) {
            int col = wn * 32 + j * 8 + 2 * tig;
            float bi0 = sbias[col], bi1 = sbias[col + 1];
            size_t m = m0g + wm * 32 + mt * 16 + g;
            float2 v0 = make_float2(d[mt][j][0] + bi0, d[mt][j][1] + bi1);
            float2 v1 = make_float2(d[mt][j][2] + bi0, d[mt][j][3] + bi1);
            *(float2*)&g_xg[m * G4 + n0g + col]       = v0;
            *(float2*)&g_xg[(m + 8) * G4 + n0g + col] = v1;
        }
    }
}

// ---------------------------------------------------------------------------
// Persistent recurrent kernel, tf32 mma. 128 CTAs, grid barrier per step.
// CTA = 32 batch rows x 16 hidden cols (64 permuted gate cols). W_hh slice
// lives in smem for all 1024 steps (frag-permuted, tf32-rounded).
// smem: Wsm 32768 floats (128KB) + Hsm 16384 floats (64KB) = 192KB dynamic.
// ---------------------------------------------------------------------------
__global__ void __launch_bounds__(256) lstm_seq_mma(
    const float* __restrict__ w_hh, int store_hs)
{
    extern __shared__ float smem[];
    float* Wsm = smem;            // [nt(8)][kt(64)][lane(32)][p(2)]
    float* Hsm = smem + 32768;    // [mt(2)][kt(64)][lane(32)][e(4)]

    int tid = threadIdx.x, lane = tid & 31, warp = tid >> 5;
    int wm = warp & 1, wn = warp >> 1;
    int g = lane >> 2, tig = lane & 3;
    int bt = blockIdx.x & 3, ct = blockIdx.x >> 2;
    int b0 = bt * 32, j0 = ct * 16;

    // ---- fill Wsm once ----
#pragma unroll 1
    for (int it = 0; it < 128; it++) {
        int fi = it * 256 + tid;
        int p = fi & 1, ln = (fi >> 1) & 31, kt = (fi >> 6) & 63, nt = fi >> 12;
        int k  = kt * 8 + (ln & 3) + 4 * p;
        int nl = nt * 8 + (ln >> 2);
        int row = (nl & 3) * Hz + j0 + (nl >> 2);
        Wsm[fi] = rna_tf32(w_hh[(size_t)row * Hz + k]);
    }
    __syncthreads();

    float cst[2] = {0.0f, 0.0f};
    int cur = 0;
    int odd = tig & 1;
    int rl = wm * 16 + g + 8 * odd;
    int b  = b0 + rl;

#pragma unroll 1
    for (int t = 0; t < Tz; t++) {
        // ---- copy permuted h tile: global -> smem (straight copy) ----
        const float* src = &g_ph[cur][bt * 16384];
#pragma unroll
        for (int i = 0; i < 16; i++) {
            int idx = (i * 256 + tid) * 4;
            float4 v = __ldcg((const float4*)&src[idx]);
            *(float4*)&Hsm[idx] = v;
        }
        __syncthreads();

        float d[2][4];
#pragma unroll
        for (int a = 0; a < 2; a++)
#pragma unroll
            for (int c = 0; c < 4; c++) d[a][c] = 0.0f;

#pragma unroll 8
        for (int kt = 0; kt < 64; kt++) {
            uint4 a   = *(uint4*)&Hsm[((wm * 64 + kt) * 32 + lane) * 4];
            uint2 bb0 = *(uint2*)&Wsm[(((wn * 2 + 0) * 64 + kt) * 32 + lane) * 2];
            uint2 bb1 = *(uint2*)&Wsm[(((wn * 2 + 1) * 64 + kt) * 32 + lane) * 2];
            mma_tf32(d[0], a, bb0);
            mma_tf32(d[1], a, bb1);
        }

        // ---- epilogue: reassemble 4 gates per cell via pair exchange ----
        float* nxt = &g_ph[cur ^ 1][bt * 16384];
#pragma unroll
        for (int tau = 0; tau < 2; tau++) {
            float p0 = __shfl_xor_sync(0xffffffffu, d[tau][0], 1);
            float p1 = __shfl_xor_sync(0xffffffffu, d[tau][1], 1);
            float p2 = __shfl_xor_sync(0xffffffffu, d[tau][2], 1);
            float p3 = __shfl_xor_sync(0xffffffffu, d[tau][3], 1);
            float gi, gf, gg, go;
            if (!odd) { gi = d[tau][0]; gf = d[tau][1]; gg = p0;        go = p1; }
            else      { gi = p2;        gf = p3;        gg = d[tau][2]; go = d[tau][3]; }

            int jjloc = wn * 4 + tau * 2 + (tig >> 1);
            float4 xv = *(const float4*)
                &g_xg[((size_t)b * Tz + t) * G4 + ct * 64 + jjloc * 4];
            gi += xv.x; gf += xv.y; gg += xv.z; go += xv.w;

            float i_ = sigf(gi), f_ = sigf(gf), g_ = tanhf(gg), o_ = sigf(go);
            float c = f_ * cst[tau] + i_ * g_;
            cst[tau] = c;
            float h = o_ * tanhf(c);

            int jc = j0 + jjloc;
            int kt2 = jc >> 3, cc = jc & 7, tg2 = cc & 3, j2 = cc >> 2;
            nxt[((wm * 64 + kt2) * 32 + g * 4 + tg2) * 4 + (odd + 2 * j2)] = rna_tf32(h);
            if (store_hs)   g_hs[((size_t)b * Tz + t) * Hz + jc] = h;
            if (t == Tz - 1) g_hlast[b * Hz + jc] = h;
        }
        cur ^= 1;

        // ---- grid barrier ----
        __threadfence();
        __syncthreads();
        if (tid == 0) {
            unsigned gen = *(volatile unsigned*)&g_gen;
            int old = atomicAdd(&g_cnt, 1);
            if (old == NCTA - 1) {
                atomicExch(&g_cnt, 0);
                __threadfence();
                atomicAdd(&g_gen, 1);
            } else {
                while (*(volatile unsigned*)&g_gen == gen) { }
            }
            __threadfence();
        }
        __syncthreads();
    }
}

// ---------------------------------------------------------------------------
__global__ void head_kernel(const float* __restrict__ fc_w,
                            const float* __restrict__ fc_b,
                            const float* __restrict__ fc2_w,
                            const float* __restrict__ fc2_b,
                            float* __restrict__ out)
{
    int b = blockIdx.x;
    int f = threadIdx.x;
    const float* hb = &g_hlast[b * Hz];
    float s = 0.0f;
    for (int k = 0; k < Hz; k += 4) {
        float4 hv = *(const float4*)&hb[k];
        float4 wv = *(const float4*)&fc_w[(size_t)f * Hz + k];
        s = fmaf(hv.x, wv.x, s);
        s = fmaf(hv.y, wv.y, s);
        s = fmaf(hv.z, wv.z, s);
        s = fmaf(hv.w, wv.w, s);
    }
    s += fc_b[f];
    s = fmaxf(s, 0.0f);
    float v = s * fc2_w[f];

    __shared__ float red[64];
    red[f] = v;
    __syncthreads();
    if (f == 0) {
        float z = 0.0f;
#pragma unroll
        for (int i = 0; i < 64; i++) z += red[i];
        z += fc2_b[0];
        out[b] = 1.0f / (1.0f + expf(-z));
    }
}

// ---------------------------------------------------------------------------
extern "C" void kernel_launch(void* const* d_in, const int* in_sizes, int n_in,
                              void* d_out, int out_size)
{
    const float* x      = (const float*)d_in[0];
    const float* w_ih0  = (const float*)d_in[2];
    const float* w_hh0  = (const float*)d_in[3];
    const float* b_ih0  = (const float*)d_in[4];
    const float* b_hh0  = (const float*)d_in[5];
    const float* w_ih1  = (const float*)d_in[6];
    const float* w_hh1  = (const float*)d_in[7];
    const float* b_ih1  = (const float*)d_in[8];
    const float* b_hh1  = (const float*)d_in[9];
    const float* fc_w   = (const float*)d_in[10];
    const float* fc_b   = (const float*)d_in[11];
    const float* fc2_w  = (const float*)d_in[12];
    const float* fc2_b  = (const float*)d_in[13];
    float* out = (float*)d_out;

    cudaFuncSetAttribute(lstm_seq_mma,
                         cudaFuncAttributeMaxDynamicSharedMemorySize, 196608);

    dim3 ggrid(G4 / 64, (Bz * Tz) / 128);   // (32, 1024)

    // Layer 0
    zero_ph_kernel<<<(2 * Bz * Hz + 255) / 256, 256>>>();
    gemm_tf32_kernel<INz, false><<<ggrid, 256>>>(x, w_ih0, b_ih0, b_hh0);
    lstm_seq_mma<<<NCTA, 256, 196608>>>(w_hh0, 1);

    // Layer 1
    zero_ph_kernel<<<(2 * Bz * Hz + 255) / 256, 256>>>();
    gemm_tf32_kernel<Hz, true><<<ggrid, 256>>>(nullptr, w_ih1, b_ih1, b_hh1);
    lstm_seq_mma<<<NCTA, 256, 196608>>>(w_hh1, 0);

    // FC head
    head_kernel<<<Bz, 64>>>(fc_w, fc_b, fc2_w, fc2_b, out);
}

// round 4
// speedup vs baseline: 3.9700x; 1.7010x over previous
#include <cuda_runtime.h>
#include <cuda_bf16.h>
#include <math.h>
#include <stdint.h>

#define Bz   128
#define Tz   1024
#define INz  256
#define Hz   512
#define G4   2048   // 4*H
#define NCTA 128

// ---------------- scratch (device globals) ---------------------------------
__device__ float g_xg[(size_t)Bz * Tz * G4];    // gate preacts, PERMUTED cols (jj*4+gate)
__device__ float g_hs[(size_t)Bz * Tz * Hz];    // layer-0 hidden outputs (plain layout)
__device__ unsigned g_phb[2][4][8192];          // h exchange, bf16 A-frag layout, 32KB per bt
__device__ float g_hlast[Bz * Hz];              // final h of the running layer
__device__ unsigned g_genA[4 * 32];             // per-group barrier generation (padded)
__device__ unsigned g_cntA[4 * 32];             // per-group arrival counter (monotonic)

// ---------------------------------------------------------------------------
__device__ __forceinline__ float rna_tf32(float x) {
    unsigned u;
    asm("cvt.rna.tf32.f32 %0, %1;" : "=r"(u) : "f"(x));
    return __uint_as_float(u);
}
__device__ __forceinline__ void mma_tf32(float* d, const uint4& a, const uint2& b) {
    asm volatile(
        "mma.sync.aligned.m16n8k8.row.col.f32.tf32.tf32.f32 "
        "{%0,%1,%2,%3}, {%4,%5,%6,%7}, {%8,%9}, {%0,%1,%2,%3};\n"
        : "+f"(d[0]), "+f"(d[1]), "+f"(d[2]), "+f"(d[3])
        : "r"(a.x), "r"(a.y), "r"(a.z), "r"(a.w), "r"(b.x), "r"(b.y));
}
__device__ __forceinline__ void mma_bf16(float* d, const uint4& a, unsigned b0, unsigned b1) {
    asm volatile(
        "mma.sync.aligned.m16n8k16.row.col.f32.bf16.bf16.f32 "
        "{%0,%1,%2,%3}, {%4,%5,%6,%7}, {%8,%9}, {%0,%1,%2,%3};\n"
        : "+f"(d[0]), "+f"(d[1]), "+f"(d[2]), "+f"(d[3])
        : "r"(a.x), "r"(a.y), "r"(a.z), "r"(a.w), "r"(b0), "r"(b1));
}
__device__ __forceinline__ float tanha(float x) {
    float y; asm("tanh.approx.f32 %0, %1;" : "=f"(y) : "f"(x)); return y;
}
__device__ __forceinline__ float siga(float x) { return 0.5f * tanha(0.5f * x) + 0.5f; }
__device__ __forceinline__ unsigned pack_bf16x2(float x, float y) {
    __nv_bfloat162 v = __floats2bfloat162_rn(x, y);
    return *(unsigned*)&v;
}

// ---------------------------------------------------------------------------
__global__ void zero_ph_kernel() {
    int i = blockIdx.x * blockDim.x + threadIdx.x;
    if (i < 2 * 4 * 8192) ((unsigned*)g_phb)[i] = 0u;
}

// ---------------------------------------------------------------------------
// Input GEMM (unchanged from R2): tf32 mma, permuted gate-col output.
// ---------------------------------------------------------------------------
template <int K, bool XFROMHS>
__global__ void __launch_bounds__(256) gemm_tf32_kernel(
    const float* __restrict__ Xin, const float* __restrict__ W,
    const float* __restrict__ b1, const float* __restrict__ b2)
{
    __shared__ float Asm[8][2][32][4];
    __shared__ float Bsm[8][2][32][2];
    __shared__ float sbias[64];

    const float* __restrict__ X = XFROMHS ? (const float*)g_hs : Xin;

    int tid  = threadIdx.x;
    int lane = tid & 31, warp = tid >> 5;
    int wm = warp & 3, wn = warp >> 2;
    int g  = lane >> 2, tig = lane & 3;
    size_t m0g = (size_t)blockIdx.y * 128;
    int    n0g = blockIdx.x * 64;

    if (tid < 64) {
        int ng  = n0g + tid;
        int row = (ng & 3) * Hz + (ng >> 2);
        sbias[tid] = b1[row] + b2[row];
    }

    float d[2][4][4];
#pragma unroll
    for (int a = 0; a < 2; a++)
#pragma unroll
        for (int b = 0; b < 4; b++)
#pragma unroll
            for (int c = 0; c < 4; c++) d[a][b][c] = 0.0f;

    int fn = tid >> 2, fq = tid & 3;
    int brow = ((n0g + fn) & 3) * Hz + ((n0g + fn) >> 2);
    const float* bbase = &W[(size_t)brow * K + fq * 4];
    int bt_ = fn >> 3, bg = fn & 7;
    int bks = fq >> 1, bp = fq & 1;

    for (int kb = 0; kb < K; kb += 16) {
#pragma unroll
        for (int i = 0; i < 2; i++) {
            int f4 = tid * 2 + i;
            int m = f4 >> 2, q = f4 & 3;
            float4 v = *(const float4*)&X[(m0g + m) * K + kb + q * 4];
            int mt = m >> 4, r = m & 15, gg = r & 7, ii = r >> 3;
            int ks = q >> 1, jj = q & 1, e = ii + 2 * jj;
            Asm[mt][ks][gg * 4 + 0][e] = rna_tf32(v.x);
            Asm[mt][ks][gg * 4 + 1][e] = rna_tf32(v.y);
            Asm[mt][ks][gg * 4 + 2][e] = rna_tf32(v.z);
            Asm[mt][ks][gg * 4 + 3][e] = rna_tf32(v.w);
        }
        {
            float4 v = *(const float4*)&bbase[kb];
            Bsm[bt_][bks][bg * 4 + 0][bp] = rna_tf32(v.x);
            Bsm[bt_][bks][bg * 4 + 1][bp] = rna_tf32(v.y);
            Bsm[bt_][bks][bg * 4 + 2][bp] = rna_tf32(v.z);
            Bsm[bt_][bks][bg * 4 + 3][bp] = rna_tf32(v.w);
        }
        __syncthreads();
#pragma unroll
        for (int ks = 0; ks < 2; ks++) {
            uint4 a0 = *(uint4*)&Asm[wm * 2 + 0][ks][lane][0];
            uint4 a1 = *(uint4*)&Asm[wm * 2 + 1][ks][lane][0];
#pragma unroll
            for (int j = 0; j < 4; j++) {
                uint2 bb = *(uint2*)&Bsm[wn * 4 + j][ks][lane][0];
                mma_tf32(d[0][j], a0, bb);
                mma_tf32(d[1][j], a1, bb);
            }
        }
        __syncthreads();
    }

#pragma unroll
    for (int mt = 0; mt < 2; mt++) {
#pragma unroll
        for (int j = 0; j < 4; j++) {
            int col = wn * 32 + j * 8 + 2 * tig;
            float bi0 = sbias[col], bi1 = sbias[col + 1];
            size_t m = m0g + wm * 32 + mt * 16 + g;
            float2 v0 = make_float2(d[mt][j][0] + bi0, d[mt][j][1] + bi1);
            float2 v1 = make_float2(d[mt][j][2] + bi0, d[mt][j][3] + bi1);
            *(float2*)&g_xg[m * G4 + n0g + col]       = v0;
            *(float2*)&g_xg[(m + 8) * G4 + n0g + col] = v1;
        }
    }
}

// ---------------------------------------------------------------------------
// Persistent recurrent kernel, bf16 m16n8k16 mma, W_hh in registers.
// 128 CTAs = 4 batch tiles x 32 col tiles. Barrier only within a batch tile
// group (32 CTAs) via acq_rel atomics (no full membar).
// CTA: 32 rows x 16 hidden cols. Warps 2(m) x 4(n). smem: 32KB h tile.
// ---------------------------------------------------------------------------
__global__ void __launch_bounds__(256, 1) lstm_seq_bf16(
    const float* __restrict__ w_hh, int store_hs)
{
    __shared__ uint4 Hsm[2][32][32];   // [mt][ks][lane] A-fragments, 32KB

    int tid = threadIdx.x, lane = tid & 31, warp = tid >> 5;
    int wm = warp & 1, wn = warp >> 1;          // wn 0..3
    int g = lane >> 2, tig = lane & 3;
    int bt = blockIdx.x & 3, ct = blockIdx.x >> 2;
    int b0 = bt * 32, j0 = ct * 16;
    int odd = tig & 1;
    int rl  = wm * 16 + g + 8 * odd;            // row this thread's cells live in
    int b   = b0 + rl;

    // ---- load W_hh fragments into registers (held for all 1024 steps) ----
    unsigned wreg[2][32][2];
#pragma unroll
    for (int nt = 0; nt < 2; nt++) {
        int nl  = (wn * 2 + nt) * 8 + g;                    // permuted gate col 0..63
        int row = (nl & 3) * Hz + j0 + (nl >> 2);
        const float* wr = &w_hh[(size_t)row * Hz];
#pragma unroll
        for (int ks = 0; ks < 32; ks++) {
#pragma unroll
            for (int r = 0; r < 2; r++) {
                float2 wv = *(const float2*)&wr[ks * 16 + 8 * r + 2 * tig];
                wreg[nt][ks][r] = pack_bf16x2(wv.x, wv.y);
            }
        }
    }

    float cst[2] = {0.0f, 0.0f};
    int cur = 0;
    unsigned* cnt = &g_cntA[bt * 32];
    unsigned* gen = &g_genA[bt * 32];

#pragma unroll 1
    for (int t = 0; t < Tz; t++) {
        // ---- prefetch xg for this step (independent of h) ----
        float4 xv[2];
#pragma unroll
        for (int nt = 0; nt < 2; nt++) {
            int jjloc = (wn * 2 + nt) * 2 + (tig >> 1);
            xv[nt] = *(const float4*)
                &g_xg[((size_t)b * Tz + t) * G4 + ct * 64 + jjloc * 4];
        }

        // ---- copy h tile (bf16 frag layout): global -> smem ----
        {
            const uint4* src = (const uint4*)&g_phb[cur][bt][0];
            uint4* dstf = &Hsm[0][0][0];
#pragma unroll
            for (int i = 0; i < 8; i++) {
                int idx = i * 256 + tid;
                dstf[idx] = __ldcg(&src[idx]);
            }
        }
        __syncthreads();

        float d[2][4];
#pragma unroll
        for (int a = 0; a < 2; a++)
#pragma unroll
            for (int c = 0; c < 4; c++) d[a][c] = 0.0f;

#pragma unroll
        for (int ks = 0; ks < 32; ks++) {
            uint4 a = Hsm[wm][ks][lane];
            mma_bf16(d[0], a, wreg[0][ks][0], wreg[0][ks][1]);
            mma_bf16(d[1], a, wreg[1][ks][0], wreg[1][ks][1]);
        }

        // ---- epilogue: gate exchange (lane^1), nonlinearity, h store ----
        __nv_bfloat16* hdst = (__nv_bfloat16*)&g_phb[cur ^ 1][bt][0];
#pragma unroll
        for (int nt = 0; nt < 2; nt++) {
            float p0 = __shfl_xor_sync(0xffffffffu, d[nt][0], 1);
            float p1 = __shfl_xor_sync(0xffffffffu, d[nt][1], 1);
            float p2 = __shfl_xor_sync(0xffffffffu, d[nt][2], 1);
            float p3 = __shfl_xor_sync(0xffffffffu, d[nt][3], 1);
            float gi, gf, gg, go;
            if (!odd) { gi = d[nt][0]; gf = d[nt][1]; gg = p0;       go = p1; }
            else      { gi = p2;       gf = p3;       gg = d[nt][2]; go = d[nt][3]; }

            gi += xv[nt].x; gf += xv[nt].y; gg += xv[nt].z; go += xv[nt].w;

            float i_ = siga(gi), f_ = siga(gf), g_ = tanha(gg), o_ = siga(go);
            float c = f_ * cst[nt] + i_ * g_;
            cst[nt] = c;
            float h = o_ * tanha(c);

            int jjloc = (wn * 2 + nt) * 2 + (tig >> 1);
            int kc = jjloc >> 3, tg2 = (jjloc & 7) >> 1, lo = jjloc & 1;
            int u16idx = ((wm * 32 + ct) * 32 + g * 4 + tg2) * 8
                       + (odd + 2 * kc) * 2 + lo;
            hdst[u16idx] = __float2bfloat16_rn(h);

            int jc = j0 + jjloc;
            if (store_hs)    g_hs[((size_t)b * Tz + t) * Hz + jc] = h;
            if (t == Tz - 1) g_hlast[b * Hz + jc] = h;
        }
        cur ^= 1;

        // ---- group barrier (32 CTAs sharing this batch tile) ----
        __syncthreads();
        if (tid == 0) {
            unsigned gen0;
            asm volatile("ld.relaxed.gpu.global.u32 %0, [%1];"
                         : "=r"(gen0) : "l"(gen) : "memory");
            unsigned old;
            asm volatile("atom.acq_rel.gpu.global.add.u32 %0, [%1], 1;"
                         : "=r"(old) : "l"(cnt) : "memory");
            if ((old & 31u) == 31u) {
                asm volatile("red.release.gpu.global.add.u32 [%0], 1;"
                             :: "l"(gen) : "memory");
            } else {
                unsigned curgen;
                do {
                    asm volatile("ld.acquire.gpu.global.u32 %0, [%1];"
                                 : "=r"(curgen) : "l"(gen) : "memory");
                } while (curgen == gen0);
            }
        }
        __syncthreads();
    }
}

// ---------------------------------------------------------------------------
__global__ void head_kernel(const float* __restrict__ fc_w,
                            const float* __restrict__ fc_b,
                            const float* __restrict__ fc2_w,
                            const float* __restrict__ fc2_b,
                            float* __restrict__ out)
{
    int b = blockIdx.x;
    int f = threadIdx.x;
    const float* hb = &g_hlast[b * Hz];
    float s = 0.0f;
    for (int k = 0; k < Hz; k += 4) {
        float4 hv = *(const float4*)&hb[k];
        float4 wv = *(const float4*)&fc_w[(size_t)f * Hz + k];
        s = fmaf(hv.x, wv.x, s);
        s = fmaf(hv.y, wv.y, s);
        s = fmaf(hv.z, wv.z, s);
        s = fmaf(hv.w, wv.w, s);
    }
    s += fc_b[f];
    s = fmaxf(s, 0.0f);
    float v = s * fc2_w[f];

    __shared__ float red[64];
    red[f] = v;
    __syncthreads();
    if (f == 0) {
        float z = 0.0f;
#pragma unroll
        for (int i = 0; i < 64; i++) z += red[i];
        z += fc2_b[0];
        out[b] = 1.0f / (1.0f + expf(-z));
    }
}

// ---------------------------------------------------------------------------
extern "C" void kernel_launch(void* const* d_in, const int* in_sizes, int n_in,
                              void* d_out, int out_size)
{
    const float* x      = (const float*)d_in[0];
    const float* w_ih0  = (const float*)d_in[2];
    const float* w_hh0  = (const float*)d_in[3];
    const float* b_ih0  = (const float*)d_in[4];
    const float* b_hh0  = (const float*)d_in[5];
    const float* w_ih1  = (const float*)d_in[6];
    const float* w_hh1  = (const float*)d_in[7];
    const float* b_ih1  = (const float*)d_in[8];
    const float* b_hh1  = (const float*)d_in[9];
    const float* fc_w   = (const float*)d_in[10];
    const float* fc_b   = (const float*)d_in[11];
    const float* fc2_w  = (const float*)d_in[12];
    const float* fc2_b  = (const float*)d_in[13];
    float* out = (float*)d_out;

    dim3 ggrid(G4 / 64, (Bz * Tz) / 128);   // (32, 1024)
    int nz = (2 * 4 * 8192 + 255) / 256;

    // Layer 0
    zero_ph_kernel<<<nz, 256>>>();
    gemm_tf32_kernel<INz, false><<<ggrid, 256>>>(x, w_ih0, b_ih0, b_hh0);
    lstm_seq_bf16<<<NCTA, 256>>>(w_hh0, 1);

    // Layer 1
    zero_ph_kernel<<<nz, 256>>>();
    gemm_tf32_kernel<Hz, true><<<ggrid, 256>>>(nullptr, w_ih1, b_ih1, b_hh1);
    lstm_seq_bf16<<<NCTA, 256>>>(w_hh1, 0);

    // FC head
    head_kernel<<<Bz, 64>>>(fc_w, fc_b, fc2_w, fc2_b, out);
}

// round 5
// speedup vs baseline: 4.2999x; 1.0831x over previous
#include <cuda_runtime.h>
#include <cuda_bf16.h>
#include <math.h>
#include <stdint.h>

#define Bz   128
#define Tz   1024
#define INz  256
#define Hz   512
#define G4   2048   // 4*H
#define NCTA 128

// ---------------- scratch (device globals) ---------------------------------
__device__ float g_xg[(size_t)Bz * Tz * G4];       // gate preacts, PERMUTED cols
__device__ __nv_bfloat16 g_hsb[(size_t)Bz * Tz * Hz]; // layer-0 hidden outputs, bf16 plain
__device__ unsigned g_phb[2][4][8192];             // h exchange, bf16 A-frag layout
__device__ float g_hlast[Bz * Hz];                 // final h of running layer
__device__ unsigned g_flag[4][32];                 // per-CTA progress flags (per bt group)

// ---------------------------------------------------------------------------
__device__ __forceinline__ void mma_bf16(float* d, const uint4& a, unsigned b0, unsigned b1) {
    asm volatile(
        "mma.sync.aligned.m16n8k16.row.col.f32.bf16.bf16.f32 "
        "{%0,%1,%2,%3}, {%4,%5,%6,%7}, {%8,%9}, {%0,%1,%2,%3};\n"
        : "+f"(d[0]), "+f"(d[1]), "+f"(d[2]), "+f"(d[3])
        : "r"(a.x), "r"(a.y), "r"(a.z), "r"(a.w), "r"(b0), "r"(b1));
}
__device__ __forceinline__ float tanha(float x) {
    float y; asm("tanh.approx.f32 %0, %1;" : "=f"(y) : "f"(x)); return y;
}
__device__ __forceinline__ float siga(float x) { return 0.5f * tanha(0.5f * x) + 0.5f; }
__device__ __forceinline__ unsigned pack_bf16x2(float x, float y) {
    __nv_bfloat162 v = __floats2bfloat162_rn(x, y);
    return *(unsigned*)&v;
}

// ---------------------------------------------------------------------------
__global__ void zero_state_kernel() {
    int i = blockIdx.x * blockDim.x + threadIdx.x;
    if (i < 2 * 4 * 8192) ((unsigned*)g_phb)[i] = 0u;
    else if (i < 2 * 4 * 8192 + 4 * 32) ((unsigned*)g_flag)[i - 2 * 4 * 8192] = 0u;
}

// ---------------------------------------------------------------------------
// Input GEMM, bf16 m16n8k16. BM=128, BN=64, BK=32, 256 thr (4m x 2n warps).
// Output to g_xg with permuted gate cols: n' = jj*4+gate, row = (n'&3)*Hz+(n'>>2)
// ---------------------------------------------------------------------------
template <int K, bool BF16IN>
__global__ void __launch_bounds__(256) gemm_bf16_kernel(
    const float* __restrict__ Xf, const float* __restrict__ W,
    const float* __restrict__ b1, const float* __restrict__ b2)
{
    __shared__ uint4 Abuf[8][2][32];   // [m16][k16 step][lane] 8KB
    __shared__ uint2 Bbuf[8][2][32];   // [n8][k16 step][lane]  2KB
    __shared__ float sbias[64];

    const __nv_bfloat16* __restrict__ Xb = g_hsb;

    int tid = threadIdx.x, lane = tid & 31, warp = tid >> 5;
    int wm = warp & 3, wn = warp >> 2;
    int g = lane >> 2, tig = lane & 3;
    size_t m0g = (size_t)blockIdx.y * 128;
    int    n0g = blockIdx.x * 64;

    if (tid < 64) {
        int ng  = n0g + tid;
        int row = (ng & 3) * Hz + (ng >> 2);
        sbias[tid] = b1[row] + b2[row];
    }

    float d[2][4][4];
#pragma unroll
    for (int a = 0; a < 2; a++)
#pragma unroll
        for (int b = 0; b < 4; b++)
#pragma unroll
            for (int c = 0; c < 4; c++) d[a][b][c] = 0.0f;

    for (int kb = 0; kb < K; kb += 32) {
        // ---- A fill: 4 quads/thread (quad = 4 consecutive k at one row) ----
#pragma unroll
        for (int i = 0; i < 4; i++) {
            int f4 = tid * 4 + i;            // 0..1023
            int m = f4 >> 3, q = f4 & 7;
            unsigned lo_, hi_;
            if (BF16IN) {
                uint2 u = *(const uint2*)&Xb[(m0g + m) * K + kb + q * 4];
                lo_ = u.x; hi_ = u.y;
            } else {
                float4 v = *(const float4*)&Xf[(m0g + m) * K + kb + q * 4];
                lo_ = pack_bf16x2(v.x, v.y); hi_ = pack_bf16x2(v.z, v.w);
            }
            int mt = m >> 4, gg = m & 7, odd = (m >> 3) & 1;
            int ks = q >> 2, kc = (q >> 1) & 1, tg2 = (q & 1) * 2;
            int e = odd + 2 * kc;
            ((unsigned*)&Abuf[mt][ks][gg * 4 + tg2])[e]     = lo_;
            ((unsigned*)&Abuf[mt][ks][gg * 4 + tg2 + 1])[e] = hi_;
        }
        // ---- B fill: 2 quads/thread ----
#pragma unroll
        for (int i = 0; i < 2; i++) {
            int fb = tid * 2 + i;            // 0..511
            int n = fb >> 3, q = fb & 7;
            int row = ((n0g + n) & 3) * Hz + ((n0g + n) >> 2);
            float4 v = *(const float4*)&W[(size_t)row * K + kb + q * 4];
            unsigned lo_ = pack_bf16x2(v.x, v.y), hi_ = pack_bf16x2(v.z, v.w);
            int nt = n >> 3, gb = n & 7;
            int ks = q >> 2, r = (q >> 1) & 1, tg = (q & 1) * 2;
            ((unsigned*)&Bbuf[nt][ks][gb * 4 + tg])[r]     = lo_;
            ((unsigned*)&Bbuf[nt][ks][gb * 4 + tg + 1])[r] = hi_;
        }
        __syncthreads();
#pragma unroll
        for (int ks = 0; ks < 2; ks++) {
            uint4 a0 = Abuf[wm * 2 + 0][ks][lane];
            uint4 a1 = Abuf[wm * 2 + 1][ks][lane];
#pragma unroll
            for (int j = 0; j < 4; j++) {
                uint2 bb = Bbuf[wn * 4 + j][ks][lane];
                mma_bf16(d[0][j], a0, bb.x, bb.y);
                mma_bf16(d[1][j], a1, bb.x, bb.y);
            }
        }
        __syncthreads();
    }

    // ---- epilogue: add bias, store permuted (fp32) ----
#pragma unroll
    for (int mt = 0; mt < 2; mt++) {
#pragma unroll
        for (int j = 0; j < 4; j++) {
            int col = wn * 32 + j * 8 + 2 * tig;
            float bi0 = sbias[col], bi1 = sbias[col + 1];
            size_t m = m0g + wm * 32 + mt * 16 + g;
            float2 v0 = make_float2(d[mt][j][0] + bi0, d[mt][j][1] + bi1);
            float2 v1 = make_float2(d[mt][j][2] + bi0, d[mt][j][3] + bi1);
            *(float2*)&g_xg[m * G4 + n0g + col]       = v0;
            *(float2*)&g_xg[(m + 8) * G4 + n0g + col] = v1;
        }
    }
}

// ---------------------------------------------------------------------------
// Persistent recurrent kernel, bf16 mma, W_hh in registers.
// Barrier: per-CTA flag words (st.release / ld.acquire poll) — no shared-
// address atomics. h published via smem stage -> coalesced STG.128.
// ---------------------------------------------------------------------------
__global__ void __launch_bounds__(256, 1) lstm_seq_bf16(
    const float* __restrict__ w_hh, int store_hs)
{
    __shared__ uint4 Hsm[2][32][32];   // A-fragments of the 32-row h tile, 32KB
    __shared__ uint4 Hstage[2][32];    // outgoing h tile stage, 1KB

    int tid = threadIdx.x, lane = tid & 31, warp = tid >> 5;
    int wm = warp & 1, wn = warp >> 1;
    int g = lane >> 2, tig = lane & 3;
    int bt = blockIdx.x & 3, ct = blockIdx.x >> 2;
    int b0 = bt * 32, j0 = ct * 16;
    int odd = tig & 1;
    int rl  = wm * 16 + g + 8 * odd;
    int b   = b0 + rl;

    // ---- W_hh fragments into registers (held for all 1024 steps) ----
    unsigned wreg[2][32][2];
#pragma unroll
    for (int nt = 0; nt < 2; nt++) {
        int nl  = (wn * 2 + nt) * 8 + g;
        int row = (nl & 3) * Hz + j0 + (nl >> 2);
        const float* wr = &w_hh[(size_t)row * Hz];
#pragma unroll
        for (int ks = 0; ks < 32; ks++) {
#pragma unroll
            for (int r = 0; r < 2; r++) {
                float2 wv = *(const float2*)&wr[ks * 16 + 8 * r + 2 * tig];
                wreg[nt][ks][r] = pack_bf16x2(wv.x, wv.y);
            }
        }
    }

    float cst[2] = {0.0f, 0.0f};
    unsigned* flags = &g_flag[bt][0];
    uint4* buf0 = (uint4*)&g_phb[0][bt][0];
    uint4* buf1 = (uint4*)&g_phb[1][bt][0];

#pragma unroll 1
    for (int t = 0; t < Tz; t++) {
        // ---- prefetch xg (streaming; independent of h) ----
        float4 xv[2];
#pragma unroll
        for (int nt = 0; nt < 2; nt++) {
            int jjloc = (wn * 2 + nt) * 2 + (tig >> 1);
            xv[nt] = __ldcs((const float4*)
                &g_xg[((size_t)b * Tz + t) * G4 + ct * 64 + jjloc * 4]);
        }

        // ---- wait: all 32 CTAs of this group finished step t-1 ----
        if (warp == 0) {
            unsigned v;
            do {
                asm volatile("ld.acquire.gpu.global.u32 %0, [%1];"
                             : "=r"(v) : "l"(flags + lane) : "memory");
            } while (!__all_sync(0xffffffffu, (int)(v >= (unsigned)t)));
        }
        __syncthreads();

        // ---- copy h tile (frag layout): global -> smem ----
        {
            const uint4* src = (t & 1) ? buf1 : buf0;
            uint4* dstf = &Hsm[0][0][0];
#pragma unroll
            for (int i = 0; i < 8; i++) {
                int idx = i * 256 + tid;
                dstf[idx] = __ldcg(&src[idx]);
            }
        }
        __syncthreads();

        float d[2][4];
#pragma unroll
        for (int a = 0; a < 2; a++)
#pragma unroll
            for (int c = 0; c < 4; c++) d[a][c] = 0.0f;

#pragma unroll
        for (int ks = 0; ks < 32; ks++) {
            uint4 a = Hsm[wm][ks][lane];
            mma_bf16(d[0], a, wreg[0][ks][0], wreg[0][ks][1]);
            mma_bf16(d[1], a, wreg[1][ks][0], wreg[1][ks][1]);
        }

        // ---- epilogue: gate exchange, nonlinearity, stage h ----
#pragma unroll
        for (int nt = 0; nt < 2; nt++) {
            float p0 = __shfl_xor_sync(0xffffffffu, d[nt][0], 1);
            float p1 = __shfl_xor_sync(0xffffffffu, d[nt][1], 1);
            float p2 = __shfl_xor_sync(0xffffffffu, d[nt][2], 1);
            float p3 = __shfl_xor_sync(0xffffffffu, d[nt][3], 1);
            float gi, gf, gg, go;
            if (!odd) { gi = d[nt][0]; gf = d[nt][1]; gg = p0;       go = p1; }
            else      { gi = p2;       gf = p3;       gg = d[nt][2]; go = d[nt][3]; }

            gi += xv[nt].x; gf += xv[nt].y; gg += xv[nt].z; go += xv[nt].w;

            float i_ = siga(gi), f_ = siga(gf), g_ = tanha(gg), o_ = siga(go);
            float c = f_ * cst[nt] + i_ * g_;
            cst[nt] = c;
            float h = o_ * tanha(c);

            int jjloc = (wn * 2 + nt) * 2 + (tig >> 1);
            int kc = jjloc >> 3, tg2 = (jjloc & 7) >> 1, lo = jjloc & 1;
            __nv_bfloat16 hb = __float2bfloat16_rn(h);
            ((unsigned short*)&Hstage[wm][g * 4 + tg2])[(odd + 2 * kc) * 2 + lo] =
                *(unsigned short*)&hb;

            int jc = j0 + jjloc;
            if (store_hs)    g_hsb[((size_t)b * Tz + t) * Hz + jc] = hb;
            if (t == Tz - 1) g_hlast[b * Hz + jc] = h;
        }

        // ---- publish: coalesced STG.128, then release flag ----
        __syncthreads();
        if (tid < 64) {
            int w = tid >> 5, l = tid & 31;
            uint4* dst = (t & 1) ? buf0 : buf1;
            dst[(w * 32 + ct) * 32 + l] = Hstage[w][l];
        }
        __syncthreads();
        if (tid == 0) {
            asm volatile("st.release.gpu.global.u32 [%0], %1;"
                         :: "l"(flags + ct), "r"((unsigned)(t + 1)) : "memory");
        }
    }
}

// ---------------------------------------------------------------------------
__global__ void head_kernel(const float* __restrict__ fc_w,
                            const float* __restrict__ fc_b,
                            const float* __restrict__ fc2_w,
                            const float* __restrict__ fc2_b,
                            float* __restrict__ out)
{
    int b = blockIdx.x;
    int f = threadIdx.x;
    const float* hb = &g_hlast[b * Hz];
    float s = 0.0f;
    for (int k = 0; k < Hz; k += 4) {
        float4 hv = *(const float4*)&hb[k];
        float4 wv = *(const float4*)&fc_w[(size_t)f * Hz + k];
        s = fmaf(hv.x, wv.x, s);
        s = fmaf(hv.y, wv.y, s);
        s = fmaf(hv.z, wv.z, s);
        s = fmaf(hv.w, wv.w, s);
    }
    s += fc_b[f];
    s = fmaxf(s, 0.0f);
    float v = s * fc2_w[f];

    __shared__ float red[64];
    red[f] = v;
    __syncthreads();
    if (f == 0) {
        float z = 0.0f;
#pragma unroll
        for (int i = 0; i < 64; i++) z += red[i];
        z += fc2_b[0];
        out[b] = 1.0f / (1.0f + expf(-z));
    }
}

// ---------------------------------------------------------------------------
extern "C" void kernel_launch(void* const* d_in, const int* in_sizes, int n_in,
                              void* d_out, int out_size)
{
    const float* x      = (const float*)d_in[0];
    const float* w_ih0  = (const float*)d_in[2];
    const float* w_hh0  = (const float*)d_in[3];
    const float* b_ih0  = (const float*)d_in[4];
    const float* b_hh0  = (const float*)d_in[5];
    const float* w_ih1  = (const float*)d_in[6];
    const float* w_hh1  = (const float*)d_in[7];
    const float* b_ih1  = (const float*)d_in[8];
    const float* b_hh1  = (const float*)d_in[9];
    const float* fc_w   = (const float*)d_in[10];
    const float* fc_b   = (const float*)d_in[11];
    const float* fc2_w  = (const float*)d_in[12];
    const float* fc2_b  = (const float*)d_in[13];
    float* out = (float*)d_out;

    dim3 ggrid(G4 / 64, (Bz * Tz) / 128);   // (32, 1024)
    int nz = (2 * 4 * 8192 + 4 * 32 + 255) / 256;

    // Layer 0
    zero_state_kernel<<<nz, 256>>>();
    gemm_bf16_kernel<INz, false><<<ggrid, 256>>>(x, w_ih0, b_ih0, b_hh0);
    lstm_seq_bf16<<<NCTA, 256>>>(w_hh0, 1);

    // Layer 1
    zero_state_kernel<<<nz, 256>>>();
    gemm_bf16_kernel<Hz, true><<<ggrid, 256>>>(nullptr, w_ih1, b_ih1, b_hh1);
    lstm_seq_bf16<<<NCTA, 256>>>(w_hh1, 0);

    // FC head
    head_kernel<<<Bz, 64>>>(fc_w, fc_b, fc2_w, fc2_b, out);
}

// round 6
// speedup vs baseline: 4.3964x; 1.0224x over previous
#include <cuda_runtime.h>
#include <cuda_bf16.h>
#include <math.h>
#include <stdint.h>

#define Bz   128
#define Tz   1024
#define INz  256
#define Hz   512
#define G4   2048   // 4*H
#define NCTA 128

// ---------------- scratch (device globals) ---------------------------------
__device__ float g_xg[(size_t)Bz * Tz * G4];       // gate preacts, PERMUTED cols
__device__ __nv_bfloat16 g_hsb[(size_t)Bz * Tz * Hz]; // layer-0 hidden outputs, bf16 plain
__device__ unsigned g_phb[2][4][8192];             // h exchange, bf16 A-frag layout
__device__ float g_hlast[Bz * Hz];                 // final h of running layer
__device__ unsigned g_flag[4][32];                 // per-CTA progress flags (per bt group)

// ---------------------------------------------------------------------------
__device__ __forceinline__ void mma_bf16(float* d, const uint4& a, unsigned b0, unsigned b1) {
    asm volatile(
        "mma.sync.aligned.m16n8k16.row.col.f32.bf16.bf16.f32 "
        "{%0,%1,%2,%3}, {%4,%5,%6,%7}, {%8,%9}, {%0,%1,%2,%3};\n"
        : "+f"(d[0]), "+f"(d[1]), "+f"(d[2]), "+f"(d[3])
        : "r"(a.x), "r"(a.y), "r"(a.z), "r"(a.w), "r"(b0), "r"(b1));
}
__device__ __forceinline__ float tanha(float x) {
    float y; asm("tanh.approx.f32 %0, %1;" : "=f"(y) : "f"(x)); return y;
}
__device__ __forceinline__ float siga(float x) { return 0.5f * tanha(0.5f * x) + 0.5f; }
__device__ __forceinline__ unsigned pack_bf16x2(float x, float y) {
    __nv_bfloat162 v = __floats2bfloat162_rn(x, y);
    return *(unsigned*)&v;
}

// ---------------------------------------------------------------------------
__global__ void zero_state_kernel() {
    int i = blockIdx.x * blockDim.x + threadIdx.x;
    if (i < 2 * 4 * 8192) ((unsigned*)g_phb)[i] = 0u;
    else if (i < 2 * 4 * 8192 + 4 * 32) ((unsigned*)g_flag)[i - 2 * 4 * 8192] = 0u;
}

// ---------------------------------------------------------------------------
// Input GEMM, bf16 m16n8k16. BM=128, BN=64, BK=32, 256 thr (4m x 2n warps).
// Output to g_xg with permuted gate cols: n' = jj*4+gate, row = (n'&3)*Hz+(n'>>2)
// ---------------------------------------------------------------------------
template <int K, bool BF16IN>
__global__ void __launch_bounds__(256) gemm_bf16_kernel(
    const float* __restrict__ Xf, const float* __restrict__ W,
    const float* __restrict__ b1, const float* __restrict__ b2)
{
    __shared__ uint4 Abuf[8][2][32];   // [m16][k16 step][lane] 8KB
    __shared__ uint2 Bbuf[8][2][32];   // [n8][k16 step][lane]  2KB
    __shared__ float sbias[64];

    const __nv_bfloat16* __restrict__ Xb = g_hsb;

    int tid = threadIdx.x, lane = tid & 31, warp = tid >> 5;
    int wm = warp & 3, wn = warp >> 2;
    int g = lane >> 2, tig = lane & 3;
    size_t m0g = (size_t)blockIdx.y * 128;
    int    n0g = blockIdx.x * 64;

    if (tid < 64) {
        int ng  = n0g + tid;
        int row = (ng & 3) * Hz + (ng >> 2);
        sbias[tid] = b1[row] + b2[row];
    }

    float d[2][4][4];
#pragma unroll
    for (int a = 0; a < 2; a++)
#pragma unroll
        for (int b = 0; b < 4; b++)
#pragma unroll
            for (int c = 0; c < 4; c++) d[a][b][c] = 0.0f;

    for (int kb = 0; kb < K; kb += 32) {
        // ---- A fill: 4 quads/thread (quad = 4 consecutive k at one row) ----
#pragma unroll
        for (int i = 0; i < 4; i++) {
            int f4 = tid * 4 + i;            // 0..1023
            int m = f4 >> 3, q = f4 & 7;
            unsigned lo_, hi_;
            if (BF16IN) {
                uint2 u = *(const uint2*)&Xb[(m0g + m) * K + kb + q * 4];
                lo_ = u.x; hi_ = u.y;
            } else {
                float4 v = *(const float4*)&Xf[(m0g + m) * K + kb + q * 4];
                lo_ = pack_bf16x2(v.x, v.y); hi_ = pack_bf16x2(v.z, v.w);
            }
            int mt = m >> 4, gg = m & 7, odd = (m >> 3) & 1;
            int ks = q >> 2, kc = (q >> 1) & 1, tg2 = (q & 1) * 2;
            int e = odd + 2 * kc;
            ((unsigned*)&Abuf[mt][ks][gg * 4 + tg2])[e]     = lo_;
            ((unsigned*)&Abuf[mt][ks][gg * 4 + tg2 + 1])[e] = hi_;
        }
        // ---- B fill: 2 quads/thread ----
#pragma unroll
        for (int i = 0; i < 2; i++) {
            int fb = tid * 2 + i;            // 0..511
            int n = fb >> 3, q = fb & 7;
            int row = ((n0g + n) & 3) * Hz + ((n0g + n) >> 2);
            float4 v = *(const float4*)&W[(size_t)row * K + kb + q * 4];
            unsigned lo_ = pack_bf16x2(v.x, v.y), hi_ = pack_bf16x2(v.z, v.w);
            int nt = n >> 3, gb = n & 7;
            int ks = q >> 2, r = (q >> 1) & 1, tg = (q & 1) * 2;
            ((unsigned*)&Bbuf[nt][ks][gb * 4 + tg])[r]     = lo_;
            ((unsigned*)&Bbuf[nt][ks][gb * 4 + tg + 1])[r] = hi_;
        }
        __syncthreads();
#pragma unroll
        for (int ks = 0; ks < 2; ks++) {
            uint4 a0 = Abuf[wm * 2 + 0][ks][lane];
            uint4 a1 = Abuf[wm * 2 + 1][ks][lane];
#pragma unroll
            for (int j = 0; j < 4; j++) {
                uint2 bb = Bbuf[wn * 4 + j][ks][lane];
                mma_bf16(d[0][j], a0, bb.x, bb.y);
                mma_bf16(d[1][j], a1, bb.x, bb.y);
            }
        }
        __syncthreads();
    }

    // ---- epilogue: add bias, store permuted (fp32) ----
#pragma unroll
    for (int mt = 0; mt < 2; mt++) {
#pragma unroll
        for (int j = 0; j < 4; j++) {
            int col = wn * 32 + j * 8 + 2 * tig;
            float bi0 = sbias[col], bi1 = sbias[col + 1];
            size_t m = m0g + wm * 32 + mt * 16 + g;
            float2 v0 = make_float2(d[mt][j][0] + bi0, d[mt][j][1] + bi1);
            float2 v1 = make_float2(d[mt][j][2] + bi0, d[mt][j][3] + bi1);
            *(float2*)&g_xg[m * G4 + n0g + col]       = v0;
            *(float2*)&g_xg[(m + 8) * G4 + n0g + col] = v1;
        }
    }
}

// ---------------------------------------------------------------------------
// Persistent recurrent kernel, bf16 mma, W_hh in registers.
// Barrier: per-CTA flag words (st.release / ld.acquire poll) — no shared-
// address atomics. h published via smem stage -> coalesced STG.128.
// ---------------------------------------------------------------------------
__global__ void __launch_bounds__(256, 1) lstm_seq_bf16(
    const float* __restrict__ w_hh, int store_hs)
{
    __shared__ uint4 Hsm[2][32][32];   // A-fragments of the 32-row h tile, 32KB
    __shared__ uint4 Hstage[2][32];    // outgoing h tile stage, 1KB

    int tid = threadIdx.x, lane = tid & 31, warp = tid >> 5;
    int wm = warp & 1, wn = warp >> 1;
    int g = lane >> 2, tig = lane & 3;
    int bt = blockIdx.x & 3, ct = blockIdx.x >> 2;
    int b0 = bt * 32, j0 = ct * 16;
    int odd = tig & 1;
    int rl  = wm * 16 + g + 8 * odd;
    int b   = b0 + rl;

    // ---- W_hh fragments into registers (held for all 1024 steps) ----
    unsigned wreg[2][32][2];
#pragma unroll
    for (int nt = 0; nt < 2; nt++) {
        int nl  = (wn * 2 + nt) * 8 + g;
        int row = (nl & 3) * Hz + j0 + (nl >> 2);
        const float* wr = &w_hh[(size_t)row * Hz];
#pragma unroll
        for (int ks = 0; ks < 32; ks++) {
#pragma unroll
            for (int r = 0; r < 2; r++) {
                float2 wv = *(const float2*)&wr[ks * 16 + 8 * r + 2 * tig];
                wreg[nt][ks][r] = pack_bf16x2(wv.x, wv.y);
            }
        }
    }

    float cst[2] = {0.0f, 0.0f};
    unsigned* flags = &g_flag[bt][0];
    uint4* buf0 = (uint4*)&g_phb[0][bt][0];
    uint4* buf1 = (uint4*)&g_phb[1][bt][0];

#pragma unroll 1
    for (int t = 0; t < Tz; t++) {
        // ---- prefetch xg (streaming; independent of h) ----
        float4 xv[2];
#pragma unroll
        for (int nt = 0; nt < 2; nt++) {
            int jjloc = (wn * 2 + nt) * 2 + (tig >> 1);
            xv[nt] = __ldcs((const float4*)
                &g_xg[((size_t)b * Tz + t) * G4 + ct * 64 + jjloc * 4]);
        }

        // ---- wait: all 32 CTAs of this group finished step t-1 ----
        if (warp == 0) {
            unsigned v;
            do {
                asm volatile("ld.acquire.gpu.global.u32 %0, [%1];"
                             : "=r"(v) : "l"(flags + lane) : "memory");
            } while (!__all_sync(0xffffffffu, (int)(v >= (unsigned)t)));
        }
        __syncthreads();

        // ---- copy h tile (frag layout): global -> smem ----
        {
            const uint4* src = (t & 1) ? buf1 : buf0;
            uint4* dstf = &Hsm[0][0][0];
#pragma unroll
            for (int i = 0; i < 8; i++) {
                int idx = i * 256 + tid;
                dstf[idx] = __ldcg(&src[idx]);
            }
        }
        __syncthreads();

        float d[2][4];
#pragma unroll
        for (int a = 0; a < 2; a++)
#pragma unroll
            for (int c = 0; c < 4; c++) d[a][c] = 0.0f;

#pragma unroll
        for (int ks = 0; ks < 32; ks++) {
            uint4 a = Hsm[wm][ks][lane];
            mma_bf16(d[0], a, wreg[0][ks][0], wreg[0][ks][1]);
            mma_bf16(d[1], a, wreg[1][ks][0], wreg[1][ks][1]);
        }

        // ---- epilogue: gate exchange, nonlinearity, stage h ----
#pragma unroll
        for (int nt = 0; nt < 2; nt++) {
            float p0 = __shfl_xor_sync(0xffffffffu, d[nt][0], 1);
            float p1 = __shfl_xor_sync(0xffffffffu, d[nt][1], 1);
            float p2 = __shfl_xor_sync(0xffffffffu, d[nt][2], 1);
            float p3 = __shfl_xor_sync(0xffffffffu, d[nt][3], 1);
            float gi, gf, gg, go;
            if (!odd) { gi = d[nt][0]; gf = d[nt][1]; gg = p0;       go = p1; }
            else      { gi = p2;       gf = p3;       gg = d[nt][2]; go = d[nt][3]; }

            gi += xv[nt].x; gf += xv[nt].y; gg += xv[nt].z; go += xv[nt].w;

            float i_ = siga(gi), f_ = siga(gf), g_ = tanha(gg), o_ = siga(go);
            float c = f_ * cst[nt] + i_ * g_;
            cst[nt] = c;
            float h = o_ * tanha(c);

            int jjloc = (wn * 2 + nt) * 2 + (tig >> 1);
            int kc = jjloc >> 3, tg2 = (jjloc & 7) >> 1, lo = jjloc & 1;
            __nv_bfloat16 hb = __float2bfloat16_rn(h);
            ((unsigned short*)&Hstage[wm][g * 4 + tg2])[(odd + 2 * kc) * 2 + lo] =
                *(unsigned short*)&hb;

            int jc = j0 + jjloc;
            if (store_hs)    g_hsb[((size_t)b * Tz + t) * Hz + jc] = hb;
            if (t == Tz - 1) g_hlast[b * Hz + jc] = h;
        }

        // ---- publish: coalesced STG.128, then release flag ----
        __syncthreads();
        if (tid < 64) {
            int w = tid >> 5, l = tid & 31;
            uint4* dst = (t & 1) ? buf0 : buf1;
            dst[(w * 32 + ct) * 32 + l] = Hstage[w][l];
        }
        __syncthreads();
        if (tid == 0) {
            asm volatile("st.release.gpu.global.u32 [%0], %1;"
                         :: "l"(flags + ct), "r"((unsigned)(t + 1)) : "memory");
        }
    }
}

// ---------------------------------------------------------------------------
__global__ void head_kernel(const float* __restrict__ fc_w,
                            const float* __restrict__ fc_b,
                            const float* __restrict__ fc2_w,
                            const float* __restrict__ fc2_b,
                            float* __restrict__ out)
{
    int b = blockIdx.x;
    int f = threadIdx.x;
    const float* hb = &g_hlast[b * Hz];
    float s = 0.0f;
    for (int k = 0; k < Hz; k += 4) {
        float4 hv = *(const float4*)&hb[k];
        float4 wv = *(const float4*)&fc_w[(size_t)f * Hz + k];
        s = fmaf(hv.x, wv.x, s);
        s = fmaf(hv.y, wv.y, s);
        s = fmaf(hv.z, wv.z, s);
        s = fmaf(hv.w, wv.w, s);
    }
    s += fc_b[f];
    s = fmaxf(s, 0.0f);
    float v = s * fc2_w[f];

    __shared__ float red[64];
    red[f] = v;
    __syncthreads();
    if (f == 0) {
        float z = 0.0f;
#pragma unroll
        for (int i = 0; i < 64; i++) z += red[i];
        z += fc2_b[0];
        out[b] = 1.0f / (1.0f + expf(-z));
    }
}

// ---------------------------------------------------------------------------
extern "C" void kernel_launch(void* const* d_in, const int* in_sizes, int n_in,
                              void* d_out, int out_size)
{
    const float* x      = (const float*)d_in[0];
    const float* w_ih0  = (const float*)d_in[2];
    const float* w_hh0  = (const float*)d_in[3];
    const float* b_ih0  = (const float*)d_in[4];
    const float* b_hh0  = (const float*)d_in[5];
    const float* w_ih1  = (const float*)d_in[6];
    const float* w_hh1  = (const float*)d_in[7];
    const float* b_ih1  = (const float*)d_in[8];
    const float* b_hh1  = (const float*)d_in[9];
    const float* fc_w   = (const float*)d_in[10];
    const float* fc_b   = (const float*)d_in[11];
    const float* fc2_w  = (const float*)d_in[12];
    const float* fc2_b  = (const float*)d_in[13];
    float* out = (float*)d_out;

    dim3 ggrid(G4 / 64, (Bz * Tz) / 128);   // (32, 1024)
    int nz = (2 * 4 * 8192 + 4 * 32 + 255) / 256;

    // Layer 0
    zero_state_kernel<<<nz, 256>>>();
    gemm_bf16_kernel<INz, false><<<ggrid, 256>>>(x, w_ih0, b_ih0, b_hh0);
    lstm_seq_bf16<<<NCTA, 256>>>(w_hh0, 1);

    // Layer 1
    zero_state_kernel<<<nz, 256>>>();
    gemm_bf16_kernel<Hz, true><<<ggrid, 256>>>(nullptr, w_ih1, b_ih1, b_hh1);
    lstm_seq_bf16<<<NCTA, 256>>>(w_hh1, 0);

    // FC head
    head_kernel<<<Bz, 64>>>(fc_w, fc_b, fc2_w, fc2_b, out);
}